// round 15
// baseline (speedup 1.0000x reference)
#include <cuda_runtime.h>
#include <cstdint>
#include <cstddef>

// ---------------------------------------------------------------------------
// W8A8 dynamic linear — 3-CTA/SM hybrid: 2 IMMA CTAs + 1 dp4a CTA per SM.
//   x [M,K] fp32 -> per-row dynamic int8 quant (scale = maxabs/127, >=1e-8)
//   weight [N,K] int8 (harness widens to int32; detected + packed)
//   out [M,N] fp32 = (xq @ wq^T) * x_scale[m] * w_scale[n] + bias[n]
// Static shapes: M=4096, K=4096, N=11008.
//
// Grid = 3 * #SMs, 256 threads/CTA, __launch_bounds__(256,3) -> <=85 regs so
// 24 warps/SM co-reside: 16 IMMA warps (tensor pipe) + 8 dp4a warps (fma).
// Job = 128x64 output tile from one global atomic queue (self-balancing).
//   IMMA CTA: 8 warps, 32x32 warp tiles (4m x 2n), cp.async double buffer.
//   dp4a CTA: 8 warps, 8x4 thread tiles, R12-proven stage structure.
// ---------------------------------------------------------------------------

#define MAXM 4096
#define MAXK 4096
#define MAXN 11008

__device__ int8_t g_xq[(size_t)MAXM * MAXK];          // 16 MB
__device__ float  g_xscale[MAXM];
__device__ int8_t g_wq[(size_t)MAXN * MAXK];          // 43 MB
__device__ int    g_w_widened;
__device__ unsigned int g_job;                        // dynamic tile queue

// ------------------------------ helpers ------------------------------------
__device__ __forceinline__ uint32_t smem_u32(const void* p) {
    uint32_t a;
    asm("{ .reg .u64 t; cvta.to.shared.u64 t, %1; cvt.u32.u64 %0, t; }"
        : "=r"(a) : "l"(p));
    return a;
}

__device__ __forceinline__ uint32_t swz(uint32_t o) {   // SW128 swizzle
    return o ^ ((o >> 3) & 0x70);
}

__device__ __forceinline__ void cp_async16(uint32_t dst, const void* src) {
    asm volatile("cp.async.cg.shared.global [%0], [%1], 16;"
                 :: "r"(dst), "l"(src) : "memory");
}
#define CP_ASYNC_COMMIT() asm volatile("cp.async.commit_group;" ::: "memory")
#define CP_ASYNC_WAIT(n)  asm volatile("cp.async.wait_group %0;" :: "n"(n) : "memory")

__device__ __forceinline__ void ldsm_x4(uint32_t& r0, uint32_t& r1,
                                        uint32_t& r2, uint32_t& r3,
                                        uint32_t addr) {
    asm volatile("ldmatrix.sync.aligned.m8n8.x4.shared.b16 {%0,%1,%2,%3}, [%4];"
                 : "=r"(r0), "=r"(r1), "=r"(r2), "=r"(r3) : "r"(addr));
}

__device__ __forceinline__ void imma16832(int* d, const uint32_t* a,
                                          const uint32_t* b) {
    asm volatile(
        "mma.sync.aligned.m16n8k32.row.col.s32.s8.s8.s32 "
        "{%0,%1,%2,%3}, {%4,%5,%6,%7}, {%8,%9}, {%0,%1,%2,%3};"
        : "+r"(d[0]), "+r"(d[1]), "+r"(d[2]), "+r"(d[3])
        : "r"(a[0]), "r"(a[1]), "r"(a[2]), "r"(a[3]), "r"(b[0]), "r"(b[1]));
}

// ---------------------------------------------------------------------------
// Kernel 0a: detect weight dtype + reset job counter.
// ---------------------------------------------------------------------------
__global__ void detect_w_dtype(const int* __restrict__ w) {
    if (threadIdx.x == 0) g_job = 0;
    int bad = 0;
    for (int i = threadIdx.x; i < 8192; i += 32) {
        int v = w[i];
        bad |= (v < -128 || v > 127) ? 1 : 0;
    }
#pragma unroll
    for (int o = 16; o > 0; o >>= 1)
        bad |= __shfl_xor_sync(0xffffffffu, bad, o);
    if (threadIdx.x == 0) g_w_widened = bad ? 0 : 1;
}

// ---------------------------------------------------------------------------
// Kernel 0b: pack weights int32 -> int8 (or copy if already packed).
// ---------------------------------------------------------------------------
__device__ __forceinline__ int pack4(int4 v) {
    return (v.x & 0xff) | ((v.y & 0xff) << 8) | ((v.z & 0xff) << 16) | (v.w << 24);
}

__global__ __launch_bounds__(256) void pack_w(const int* __restrict__ w,
                                              size_t n_out16) {
    const size_t i = (size_t)blockIdx.x * 256 + threadIdx.x;
    if (i >= n_out16) return;
    int4 outv;
    if (g_w_widened) {
        const int4* src = reinterpret_cast<const int4*>(w) + i * 4;
        outv.x = pack4(src[0]);
        outv.y = pack4(src[1]);
        outv.z = pack4(src[2]);
        outv.w = pack4(src[3]);
    } else {
        outv = reinterpret_cast<const int4*>(w)[i];
    }
    reinterpret_cast<int4*>(g_wq)[i] = outv;
}

// ---------------------------------------------------------------------------
// Kernel 1: per-row maxabs -> scale -> RNE quantize -> pack.
// ---------------------------------------------------------------------------
__global__ __launch_bounds__(256) void quant_rows(const float* __restrict__ x,
                                                  int K) {
    const int m = blockIdx.x;
    const int t = threadIdx.x;
    const int K4 = K >> 2;
    const float4* __restrict__ xrow =
        reinterpret_cast<const float4*>(x + (size_t)m * K);

    float amax = 0.0f;
    for (int i = t; i < K4; i += 256) {
        float4 v = xrow[i];
        amax = fmaxf(amax, fmaxf(fmaxf(fabsf(v.x), fabsf(v.y)),
                                 fmaxf(fabsf(v.z), fabsf(v.w))));
    }

    __shared__ float red[8];
#pragma unroll
    for (int o = 16; o > 0; o >>= 1)
        amax = fmaxf(amax, __shfl_xor_sync(0xffffffffu, amax, o));
    if ((t & 31) == 0) red[t >> 5] = amax;
    __syncthreads();
    if (t < 32) {
        float a = (t < 8) ? red[t] : 0.0f;
#pragma unroll
        for (int o = 4; o > 0; o >>= 1)
            a = fmaxf(a, __shfl_xor_sync(0xffffffffu, a, o));
        if (t == 0) red[0] = a;
    }
    __syncthreads();

    const float scale = fmaxf(red[0] / 127.0f, 1e-8f);
    if (t == 0) g_xscale[m] = scale;

    int* __restrict__ outw = reinterpret_cast<int*>(g_xq + (size_t)m * K);
    for (int i = t; i < K4; i += 256) {
        float4 v = xrow[i];
        int q0 = min(127, max(-128, __float2int_rn(v.x / scale)));
        int q1 = min(127, max(-128, __float2int_rn(v.y / scale)));
        int q2 = min(127, max(-128, __float2int_rn(v.z / scale)));
        int q3 = min(127, max(-128, __float2int_rn(v.w / scale)));
        outw[i] = (q0 & 0xff) | ((q1 & 0xff) << 8) | ((q2 & 0xff) << 16)
                | (q3 << 24);
    }
}

// ---------------------------------------------------------------------------
// Kernel 2: persistent hybrid GEMM, 128x64 jobs, role by blockIdx%3.
// IMMA SMEM: A0(16K) B0(8K) A1(16K) B1(8K). dp4a SMEM: As(4K) Bs(2K).
// ---------------------------------------------------------------------------
#define SM_A0  0
#define SM_B0  16384
#define SM_A1  24576
#define SM_B1  40960
#define SM_JOB 49152
#define SM_TOTAL (SM_JOB + 32)

#define BKW 8    // dp4a: int32 words of K per stage (= 32 int8)

__global__ __launch_bounds__(256, 3)
void gemm_hybrid(const float* __restrict__ wscale,
                 const float* __restrict__ bias,
                 float* __restrict__ out,
                 int M, int N, int K) {
    extern __shared__ __align__(1024) char smem[];
    const uint32_t sbase = smem_u32(smem);
    volatile unsigned* jslot = reinterpret_cast<volatile unsigned*>(smem + SM_JOB);

    const int t = threadIdx.x;
    const int mtiles = M >> 7;                 // 32
    const unsigned njobs = (unsigned)(mtiles * (N >> 6));   // 5504
    const int Kw16 = K >> 4;

    if ((blockIdx.x % 3) != 2) {
        // ================= IMMA CTA (8 warps, 32x32 warp tiles) ============
        const int wid = t >> 5;
        const int lid = t & 31;
        const int wm  = wid >> 1;             // 0..3 (m: 32 rows each)
        const int wn  = wid & 1;              // 0..1 (n: 32 cols each)

        const int cg = t & 7;
        const int r0 = t >> 3;                // 0..31

        const int4* Abase = reinterpret_cast<const int4*>(g_xq) + cg;
        const int4* Bbase = reinterpret_cast<const int4*>(g_wq) + cg;

        const int nstage = K / 128;           // 32
        const int lrow_off = (lid & 7) + ((lid >> 3) & 1) * 8;
        const int lchunk   = lid >> 4;
        const int g   = lid >> 2;
        const int q   = lid & 3;
        const uint32_t sw_o = swz((uint32_t)r0 * 128u + (uint32_t)cg * 16u);

        int bm = 0, bn = 0;
        auto issue = [&](int kc) {
            const int4* Ag = Abase + (size_t)(kc * 8);
            const int4* Bg = Bbase + (size_t)(kc * 8);
            const uint32_t ab = sbase + ((kc & 1) ? SM_A1 : SM_A0) + sw_o;
            const uint32_t bb = sbase + ((kc & 1) ? SM_B1 : SM_B0) + sw_o;
#pragma unroll
            for (int i = 0; i < 4; i++)
                cp_async16(ab + swz((uint32_t)(32 * i) * 128u) - swz(0u) * 0u
                               + (uint32_t)(0),   // placeholder removed below
                           Ag);
            CP_ASYNC_COMMIT();
        };
        (void)issue; // not used; explicit code below for reg economy

        for (;;) {
            if (t == 0) jslot[0] = atomicAdd(&g_job, 1u);
            __syncthreads();
            const unsigned j = jslot[0];
            if (j >= njobs) break;
            bm = (int)(j % (unsigned)mtiles) * 128;
            bn = (int)(j / (unsigned)mtiles) * 64;

            int acc[2][4][4];
#pragma unroll
            for (int i = 0; i < 2; i++)
#pragma unroll
                for (int jj = 0; jj < 4; jj++)
#pragma unroll
                    for (int qq = 0; qq < 4; qq++) acc[i][jj][qq] = 0;

            // prologue: stage 0
            {
                const int4* Ag = Abase;
                const int4* Bg = Bbase;
                const uint32_t ab = sbase + SM_A0;
                const uint32_t bb = sbase + SM_B0;
#pragma unroll
                for (int i = 0; i < 4; i++)
                    cp_async16(ab + swz((uint32_t)(r0 + 32 * i) * 128u
                                        + (uint32_t)cg * 16u),
                               Ag + (size_t)(bm + r0 + 32 * i) * Kw16);
#pragma unroll
                for (int i = 0; i < 2; i++)
                    cp_async16(bb + swz((uint32_t)(r0 + 32 * i) * 128u
                                        + (uint32_t)cg * 16u),
                               Bg + (size_t)(bn + r0 + 32 * i) * Kw16);
                CP_ASYNC_COMMIT();
            }

            for (int kc = 0; kc < nstage; kc++) {
                if (kc + 1 < nstage) {
                    const int4* Ag = Abase + (size_t)((kc + 1) * 8);
                    const int4* Bg = Bbase + (size_t)((kc + 1) * 8);
                    const uint32_t ab = sbase + ((kc & 1) ? SM_A0 : SM_A1);
                    const uint32_t bb = sbase + ((kc & 1) ? SM_B0 : SM_B1);
#pragma unroll
                    for (int i = 0; i < 4; i++)
                        cp_async16(ab + swz((uint32_t)(r0 + 32 * i) * 128u
                                            + (uint32_t)cg * 16u),
                                   Ag + (size_t)(bm + r0 + 32 * i) * Kw16);
#pragma unroll
                    for (int i = 0; i < 2; i++)
                        cp_async16(bb + swz((uint32_t)(r0 + 32 * i) * 128u
                                            + (uint32_t)cg * 16u),
                                   Bg + (size_t)(bn + r0 + 32 * i) * Kw16);
                    CP_ASYNC_COMMIT();
                    CP_ASYNC_WAIT(1);
                } else {
                    CP_ASYNC_WAIT(0);
                }
                __syncthreads();

                const uint32_t sA = sbase + ((kc & 1) ? SM_A1 : SM_A0);
                const uint32_t sB = sbase + ((kc & 1) ? SM_B1 : SM_B0);

#pragma unroll
                for (int s = 0; s < 4; s++) {
                    const int c = s * 2 + lchunk;
                    uint32_t a[2][4];
#pragma unroll
                    for (int ma = 0; ma < 2; ma++) {
                        const uint32_t row =
                            (uint32_t)(wm * 32 + ma * 16 + lrow_off);
                        ldsm_x4(a[ma][0], a[ma][1], a[ma][2], a[ma][3],
                                sA + swz(row * 128u + (uint32_t)c * 16u));
                    }
                    uint32_t b[4][2];
#pragma unroll
                    for (int nb = 0; nb < 2; nb++) {
                        const uint32_t row =
                            (uint32_t)(wn * 32 + nb * 16 + lrow_off);
                        uint32_t q0, q1, q2, q3;
                        ldsm_x4(q0, q1, q2, q3,
                                sB + swz(row * 128u + (uint32_t)c * 16u));
                        b[2 * nb][0] = q0; b[2 * nb][1] = q2;
                        b[2 * nb + 1][0] = q1; b[2 * nb + 1][1] = q3;
                    }
#pragma unroll
                    for (int ma = 0; ma < 2; ma++)
#pragma unroll
                        for (int na = 0; na < 4; na++)
                            imma16832(acc[ma][na], a[ma], b[na]);
                }
                __syncthreads();
            }

            // epilogue
#pragma unroll
            for (int ma = 0; ma < 2; ma++) {
                const int m0 = bm + wm * 32 + ma * 16 + g;
                const int m1 = m0 + 8;
                const float xs0 = g_xscale[m0];
                const float xs1 = g_xscale[m1];
                float* row0 = out + (size_t)m0 * N;
                float* row1 = out + (size_t)m1 * N;
#pragma unroll
                for (int na = 0; na < 4; na++) {
                    const int n = bn + wn * 32 + na * 8 + q * 2;
                    const float ws0 = __ldg(wscale + n);
                    const float ws1 = __ldg(wscale + n + 1);
                    const float bb0 = __ldg(bias + n);
                    const float bb1 = __ldg(bias + n + 1);
                    float2 o0, o1;
                    o0.x = (float)acc[ma][na][0] * xs0 * ws0 + bb0;
                    o0.y = (float)acc[ma][na][1] * xs0 * ws1 + bb1;
                    o1.x = (float)acc[ma][na][2] * xs1 * ws0 + bb0;
                    o1.y = (float)acc[ma][na][3] * xs1 * ws1 + bb1;
                    *reinterpret_cast<float2*>(row0 + n) = o0;
                    *reinterpret_cast<float2*>(row1 + n) = o1;
                }
            }
        }
    } else {
        // ================= dp4a CTA (8 warps, 8x4 thread tiles) ============
        int* As = reinterpret_cast<int*>(smem);           // [BKW][128] 4 KB
        int* Bs = As + BKW * 128;                         // [BKW][64]  2 KB

        const int tx = t & 15;             // 0..15 -> 4 cols each
        const int ty = t >> 4;             // 0..15 -> 8 rows each
        const int arow  = t >> 1;          // 0..127
        const int ahalf = t & 1;
        const int wa    = ahalf * 4;
        const bool bact = (t < 128);
        const int brow  = t >> 1;          // 0..63 when bact

        const int nstage = (K >> 2) / BKW; // 128 stages

        for (;;) {
            if (t == 0) jslot[0] = atomicAdd(&g_job, 1u);
            __syncthreads();
            const unsigned j = jslot[0];
            if (j >= njobs) break;
            const int bm = (int)(j % (unsigned)mtiles) * 128;
            const int bn = (int)(j / (unsigned)mtiles) * 64;

            const int4* Ag = reinterpret_cast<const int4*>(g_xq) +
                             (size_t)(bm + arow) * Kw16 + ahalf;
            const int4* Bg = reinterpret_cast<const int4*>(g_wq) +
                             (size_t)(bn + brow) * Kw16 + ahalf;

            int acc[8][4];
#pragma unroll
            for (int i = 0; i < 8; i++)
#pragma unroll
                for (int jj = 0; jj < 4; jj++) acc[i][jj] = 0;

            int4 pa = Ag[0];
            int4 pb = bact ? Bg[0] : make_int4(0, 0, 0, 0);

            for (int s = 0; s < nstage; s++) {
                __syncthreads();           // previous stage's reads done

                As[(wa + 0) * 128 + arow] = pa.x;
                As[(wa + 1) * 128 + arow] = pa.y;
                As[(wa + 2) * 128 + arow] = pa.z;
                As[(wa + 3) * 128 + arow] = pa.w;
                if (bact) {
                    Bs[(wa + 0) * 64 + brow] = pb.x;
                    Bs[(wa + 1) * 64 + brow] = pb.y;
                    Bs[(wa + 2) * 64 + brow] = pb.z;
                    Bs[(wa + 3) * 64 + brow] = pb.w;
                }

                if (s + 1 < nstage) {
                    pa = Ag[(size_t)(s + 1) * 2];
                    if (bact) pb = Bg[(size_t)(s + 1) * 2];
                }

                __syncthreads();           // stores visible

#pragma unroll
                for (int kk = 0; kk < BKW; kk++) {
                    int4 af0 = *reinterpret_cast<const int4*>(&As[kk * 128 + (ty << 3)]);
                    int4 af1 = *reinterpret_cast<const int4*>(&As[kk * 128 + (ty << 3) + 4]);
                    int4 bf0 = *reinterpret_cast<const int4*>(&Bs[kk * 64 + (tx << 2)]);
                    int af[8] = {af0.x, af0.y, af0.z, af0.w, af1.x, af1.y, af1.z, af1.w};
                    int bf[4] = {bf0.x, bf0.y, bf0.z, bf0.w};
#pragma unroll
                    for (int i = 0; i < 8; i++)
#pragma unroll
                        for (int jj = 0; jj < 4; jj++)
                            acc[i][jj] = __dp4a(af[i], bf[jj], acc[i][jj]);
                }
            }

            const int cn = bn + (tx << 2);
            float4 ws = *reinterpret_cast<const float4*>(wscale + cn);
            float4 bb = *reinterpret_cast<const float4*>(bias + cn);

#pragma unroll
            for (int i = 0; i < 8; i++) {
                const int m = bm + (ty << 3) + i;
                const float xs = g_xscale[m];
                float4 o;
                o.x = (float)acc[i][0] * xs * ws.x + bb.x;
                o.y = (float)acc[i][1] * xs * ws.y + bb.y;
                o.z = (float)acc[i][2] * xs * ws.z + bb.z;
                o.w = (float)acc[i][3] * xs * ws.w + bb.w;
                *reinterpret_cast<float4*>(out + (size_t)m * N + cn) = o;
            }
        }
    }
}

// ---------------------------------------------------------------------------
// Launch
// ---------------------------------------------------------------------------
extern "C" void kernel_launch(void* const* d_in, const int* in_sizes, int n_in,
                              void* d_out, int out_size) {
    const float* x      = (const float*)d_in[0];
    const int*   weight = (const int*)d_in[1];
    const float* wscale = (const float*)d_in[2];
    const float* bias   = (const float*)d_in[3];
    float*       out    = (float*)d_out;

    const int N = in_sizes[2];           // 11008
    const int K = in_sizes[1] / N;       // 4096
    const int M = in_sizes[0] / K;       // 4096

    detect_w_dtype<<<1, 32>>>(weight);   // also resets g_job

    const size_t n_out16 = ((size_t)N * K) / 16;
    pack_w<<<(unsigned)((n_out16 + 255) / 256), 256>>>(weight, n_out16);

    quant_rows<<<M, 256>>>(x, K);

    static int nsm = 0;
    if (!nsm) {
        cudaDeviceGetAttribute(&nsm, cudaDevAttrMultiProcessorCount, 0);
        if (nsm <= 0) nsm = 148;
        cudaFuncSetAttribute(gemm_hybrid,
                             cudaFuncAttributeMaxDynamicSharedMemorySize,
                             SM_TOTAL);
    }
    gemm_hybrid<<<3 * nsm, 256, SM_TOTAL>>>(wscale, bias, out, M, N, K);
}

// round 16
// speedup vs baseline: 1.7510x; 1.7510x over previous
#include <cuda_runtime.h>
#include <cstdint>
#include <cstddef>

// ---------------------------------------------------------------------------
// W8A8 dynamic linear — persistent hybrid IMMA + dp4a (R12 structure),
// with reduced-barrier pipelines:
//   IMMA half: 3-stage cp.async ring, one bar/stage.
//   dp4a half: BKW=16 double-buffered, one bar/stage.
//   x [M,K] fp32 -> per-row dynamic int8 quant (scale = maxabs/127, >=1e-8)
//   weight [N,K] int8 (harness widens to int32; detected + packed)
//   out [M,N] fp32 = (xq @ wq^T) * x_scale[m] * w_scale[n] + bias[n]
// Static shapes: M=4096, K=4096, N=11008.
// ---------------------------------------------------------------------------

#define MAXM 4096
#define MAXK 4096
#define MAXN 11008

#define M_TILES 32                     // M/128
#define N_TILES 86                     // N/128
#define NJOBS (M_TILES * N_TILES)      // 2752

__device__ int8_t g_xq[(size_t)MAXM * MAXK];          // 16 MB
__device__ float  g_xscale[MAXM];
__device__ int8_t g_wq[(size_t)MAXN * MAXK];          // 43 MB
__device__ int    g_w_widened;
__device__ unsigned int g_job;                        // dynamic tile queue

// ------------------------------ helpers ------------------------------------
__device__ __forceinline__ uint32_t smem_u32(const void* p) {
    uint32_t a;
    asm("{ .reg .u64 t; cvta.to.shared.u64 t, %1; cvt.u32.u64 %0, t; }"
        : "=r"(a) : "l"(p));
    return a;
}

__device__ __forceinline__ uint32_t swz(uint32_t o) {   // SW128 swizzle
    return o ^ ((o >> 3) & 0x70);
}

__device__ __forceinline__ void cp_async16(uint32_t dst, const void* src) {
    asm volatile("cp.async.cg.shared.global [%0], [%1], 16;"
                 :: "r"(dst), "l"(src) : "memory");
}
#define CP_ASYNC_COMMIT() asm volatile("cp.async.commit_group;" ::: "memory")
#define CP_ASYNC_WAIT(n)  asm volatile("cp.async.wait_group %0;" :: "n"(n) : "memory")

#define BAR_SYNC(id, cnt) \
    asm volatile("bar.sync %0, %1;" :: "r"(id), "r"(cnt) : "memory")

__device__ __forceinline__ void ldsm_x4(uint32_t& r0, uint32_t& r1,
                                        uint32_t& r2, uint32_t& r3,
                                        uint32_t addr) {
    asm volatile("ldmatrix.sync.aligned.m8n8.x4.shared.b16 {%0,%1,%2,%3}, [%4];"
                 : "=r"(r0), "=r"(r1), "=r"(r2), "=r"(r3) : "r"(addr));
}

__device__ __forceinline__ void imma16832(int* d, const uint32_t* a,
                                          const uint32_t* b) {
    asm volatile(
        "mma.sync.aligned.m16n8k32.row.col.s32.s8.s8.s32 "
        "{%0,%1,%2,%3}, {%4,%5,%6,%7}, {%8,%9}, {%0,%1,%2,%3};"
        : "+r"(d[0]), "+r"(d[1]), "+r"(d[2]), "+r"(d[3])
        : "r"(a[0]), "r"(a[1]), "r"(a[2]), "r"(a[3]), "r"(b[0]), "r"(b[1]));
}

// ---------------------------------------------------------------------------
// Kernel 0a: detect weight dtype + reset job counter.
// ---------------------------------------------------------------------------
__global__ void detect_w_dtype(const int* __restrict__ w) {
    if (threadIdx.x == 0) g_job = 0;
    int bad = 0;
    for (int i = threadIdx.x; i < 8192; i += 32) {
        int v = w[i];
        bad |= (v < -128 || v > 127) ? 1 : 0;
    }
#pragma unroll
    for (int o = 16; o > 0; o >>= 1)
        bad |= __shfl_xor_sync(0xffffffffu, bad, o);
    if (threadIdx.x == 0) g_w_widened = bad ? 0 : 1;
}

// ---------------------------------------------------------------------------
// Kernel 0b: pack weights int32 -> int8 (or copy if already packed).
// ---------------------------------------------------------------------------
__device__ __forceinline__ int pack4(int4 v) {
    return (v.x & 0xff) | ((v.y & 0xff) << 8) | ((v.z & 0xff) << 16) | (v.w << 24);
}

__global__ __launch_bounds__(256) void pack_w(const int* __restrict__ w,
                                              size_t n_out16) {
    const size_t i = (size_t)blockIdx.x * 256 + threadIdx.x;
    if (i >= n_out16) return;
    int4 outv;
    if (g_w_widened) {
        const int4* src = reinterpret_cast<const int4*>(w) + i * 4;
        outv.x = pack4(src[0]);
        outv.y = pack4(src[1]);
        outv.z = pack4(src[2]);
        outv.w = pack4(src[3]);
    } else {
        outv = reinterpret_cast<const int4*>(w)[i];
    }
    reinterpret_cast<int4*>(g_wq)[i] = outv;
}

// ---------------------------------------------------------------------------
// Kernel 1: per-row maxabs -> scale -> RNE quantize -> pack.
// ---------------------------------------------------------------------------
__global__ __launch_bounds__(256) void quant_rows(const float* __restrict__ x,
                                                  int K) {
    const int m = blockIdx.x;
    const int t = threadIdx.x;
    const int K4 = K >> 2;
    const float4* __restrict__ xrow =
        reinterpret_cast<const float4*>(x + (size_t)m * K);

    float amax = 0.0f;
    for (int i = t; i < K4; i += 256) {
        float4 v = xrow[i];
        amax = fmaxf(amax, fmaxf(fmaxf(fabsf(v.x), fabsf(v.y)),
                                 fmaxf(fabsf(v.z), fabsf(v.w))));
    }

    __shared__ float red[8];
#pragma unroll
    for (int o = 16; o > 0; o >>= 1)
        amax = fmaxf(amax, __shfl_xor_sync(0xffffffffu, amax, o));
    if ((t & 31) == 0) red[t >> 5] = amax;
    __syncthreads();
    if (t < 32) {
        float a = (t < 8) ? red[t] : 0.0f;
#pragma unroll
        for (int o = 4; o > 0; o >>= 1)
            a = fmaxf(a, __shfl_xor_sync(0xffffffffu, a, o));
        if (t == 0) red[0] = a;
    }
    __syncthreads();

    const float scale = fmaxf(red[0] / 127.0f, 1e-8f);
    if (t == 0) g_xscale[m] = scale;

    int* __restrict__ outw = reinterpret_cast<int*>(g_xq + (size_t)m * K);
    for (int i = t; i < K4; i += 256) {
        float4 v = xrow[i];
        int q0 = min(127, max(-128, __float2int_rn(v.x / scale)));
        int q1 = min(127, max(-128, __float2int_rn(v.y / scale)));
        int q2 = min(127, max(-128, __float2int_rn(v.z / scale)));
        int q3 = min(127, max(-128, __float2int_rn(v.w / scale)));
        outw[i] = (q0 & 0xff) | ((q1 & 0xff) << 8) | ((q2 & 0xff) << 16)
                | (q3 << 24);
    }
}

// ---------------------------------------------------------------------------
// Kernel 2: persistent hybrid GEMM, dynamic queue.
// SMEM: IMMA ring 3 x (A 16K | B 16K) = 96K; dp4a 2 x 16K; job slots.
// ---------------------------------------------------------------------------
#define RING_STRIDE 32768              // A tile + B tile per ring slot
#define SM_RING 0                      // 3 slots: 0, 32K, 64K
#define SM_D    98304                  // dp4a: 2 x 16 KB
#define SM_JOB  131072
#define SM_TOTAL (SM_JOB + 32)

#define BKW 16   // dp4a: int32 words of K per stage (= 64 int8)

__global__ __launch_bounds__(512, 1)
void gemm_hybrid(const float* __restrict__ wscale,
                 const float* __restrict__ bias,
                 float* __restrict__ out,
                 int M, int N, int K) {
    extern __shared__ __align__(1024) char smem[];
    const uint32_t sbase = smem_u32(smem);
    volatile unsigned* jslot = reinterpret_cast<volatile unsigned*>(smem + SM_JOB);

    const int tid = threadIdx.x;
    const int Kw16 = K >> 4;

    if (tid < 256) {
        // ============ IMMA half (warps 0-7), 3-stage ring, 1 bar/stage =====
        const int t   = tid;
        const int wid = t >> 5;
        const int lid = t & 31;
        const int wm  = wid >> 2;             // 0..1
        const int wn  = wid & 3;              // 0..3

        const int cg = t & 7;
        const int r0 = t >> 3;

        const int4* Abase = reinterpret_cast<const int4*>(g_xq) + cg;
        const int4* Bbase = reinterpret_cast<const int4*>(g_wq) + cg;

        // per-thread swizzled offsets within a ring slot (A at 0, B at 16K)
        uint32_t swo[4];
#pragma unroll
        for (int i = 0; i < 4; i++)
            swo[i] = swz((uint32_t)(r0 + 32 * i) * 128u + (uint32_t)cg * 16u);

        const uint32_t ring0 = sbase + SM_RING;
        const uint32_t ring1 = ring0 + RING_STRIDE;
        const uint32_t ring2 = ring1 + RING_STRIDE;

        const int nstage = K / 128;           // 32
        const int lrow_off = (lid & 7) + ((lid >> 3) & 1) * 8;
        const int lchunk   = lid >> 4;
        const int g   = lid >> 2;
        const int q   = lid & 3;

        int bm = 0, bn = 0;
        auto issue = [&](int kc, uint32_t slotbase) {
            const int4* Ag = Abase + (size_t)(kc * 8);
            const int4* Bg = Bbase + (size_t)(kc * 8);
#pragma unroll
            for (int i = 0; i < 4; i++) {
                cp_async16(slotbase + swo[i],
                           Ag + (size_t)(bm + r0 + 32 * i) * Kw16);
                cp_async16(slotbase + 16384u + swo[i],
                           Bg + (size_t)(bn + r0 + 32 * i) * Kw16);
            }
            CP_ASYNC_COMMIT();
        };

        for (;;) {
            if (t == 0) jslot[0] = atomicAdd(&g_job, 1u);
            BAR_SYNC(1, 256);                 // also separates jobs (ring reuse)
            const unsigned j = jslot[0];
            if (j >= NJOBS) break;
            bm = (int)(j & (M_TILES - 1)) * 128;
            bn = (int)(j >> 5) * 128;

            int acc[4][4][4];
#pragma unroll
            for (int i = 0; i < 4; i++)
#pragma unroll
                for (int jj = 0; jj < 4; jj++)
#pragma unroll
                    for (int qq = 0; qq < 4; qq++) acc[i][jj][qq] = 0;

            // prologue: stages 0,1 in flight
            issue(0, ring0);
            issue(1, ring1);

            int ci = 0;                       // kc % 3
            for (int kc = 0; kc < nstage; kc++) {
                if (kc < nstage - 1) { CP_ASYNC_WAIT(1); }
                else                { CP_ASYNC_WAIT(0); }
                BAR_SYNC(1, 256);             // stage kc visible to all warps

                const uint32_t slot =
                    (ci == 0) ? ring0 : ((ci == 1) ? ring1 : ring2);
                const uint32_t sA = slot;
                const uint32_t sB = slot + 16384u;

#pragma unroll
                for (int s = 0; s < 4; s++) {
                    const int c = s * 2 + lchunk;
                    uint32_t a[4][4];
#pragma unroll
                    for (int ma = 0; ma < 4; ma++) {
                        const uint32_t row =
                            (uint32_t)(wm * 64 + ma * 16 + lrow_off);
                        ldsm_x4(a[ma][0], a[ma][1], a[ma][2], a[ma][3],
                                sA + swz(row * 128u + (uint32_t)c * 16u));
                    }
                    uint32_t b[4][2];
#pragma unroll
                    for (int nb = 0; nb < 2; nb++) {
                        const uint32_t row =
                            (uint32_t)(wn * 32 + nb * 16 + lrow_off);
                        uint32_t q0, q1, q2, q3;
                        ldsm_x4(q0, q1, q2, q3,
                                sB + swz(row * 128u + (uint32_t)c * 16u));
                        b[2 * nb][0] = q0; b[2 * nb][1] = q2;
                        b[2 * nb + 1][0] = q1; b[2 * nb + 1][1] = q3;
                    }
#pragma unroll
                    for (int ma = 0; ma < 4; ma++)
#pragma unroll
                        for (int na = 0; na < 4; na++)
                            imma16832(acc[ma][na], a[ma], b[na]);
                }

                // issue kc+2 into slot (kc+2)%3 == (kc-1)%3 — safe: the BAR
                // above proved all warps finished computing kc-1.
                if (kc + 2 < nstage) {
                    const int ii = (ci + 2 >= 3) ? ci - 1 : ci + 2;
                    const uint32_t islot =
                        (ii == 0) ? ring0 : ((ii == 1) ? ring1 : ring2);
                    issue(kc + 2, islot);
                }
                ci = (ci + 1 >= 3) ? 0 : ci + 1;
            }

            // epilogue
#pragma unroll
            for (int ma = 0; ma < 4; ma++) {
                const int m0 = bm + wm * 64 + ma * 16 + g;
                const int m1 = m0 + 8;
                const float xs0 = g_xscale[m0];
                const float xs1 = g_xscale[m1];
                float* row0 = out + (size_t)m0 * N;
                float* row1 = out + (size_t)m1 * N;
#pragma unroll
                for (int na = 0; na < 4; na++) {
                    const int n = bn + wn * 32 + na * 8 + q * 2;
                    const float ws0 = __ldg(wscale + n);
                    const float ws1 = __ldg(wscale + n + 1);
                    const float bb0 = __ldg(bias + n);
                    const float bb1 = __ldg(bias + n + 1);
                    float2 o0, o1;
                    o0.x = (float)acc[ma][na][0] * xs0 * ws0 + bb0;
                    o0.y = (float)acc[ma][na][1] * xs0 * ws1 + bb1;
                    o1.x = (float)acc[ma][na][2] * xs1 * ws0 + bb0;
                    o1.y = (float)acc[ma][na][3] * xs1 * ws1 + bb1;
                    *reinterpret_cast<float2*>(row0 + n) = o0;
                    *reinterpret_cast<float2*>(row1 + n) = o1;
                }
            }
        }
    } else {
        // ============ dp4a half (warps 8-15), BKW=16, 2 bufs, 1 bar/stage ==
        const int t = tid - 256;

        const int tx = t & 15;
        const int ty = t >> 4;
        const int lrow = t >> 1;           // 0..127: row this thread fills
        const int ch0  = (t & 1) * 2;      // int4 cols {0,1} or {2,3} of stage
        const int wa   = ch0 * 4;          // first word column

        const int nstage = (K >> 2) / BKW; // 64 stages of 64B

        int* buf0 = reinterpret_cast<int*>(smem + SM_D);          // [16][128]x2
        int* buf1 = reinterpret_cast<int*>(smem + SM_D + 16384);

        for (;;) {
            if (t == 0) jslot[1] = atomicAdd(&g_job, 1u);
            BAR_SYNC(2, 256);
            const unsigned j = jslot[1];
            if (j >= NJOBS) break;
            const int bm = (int)(j & (M_TILES - 1)) * 128;
            const int bn = (int)(j >> 5) * 128;

            // stage s: global int4 index = s*4 + ch0 (+1)
            const int4* Ag = reinterpret_cast<const int4*>(g_xq) +
                             (size_t)(bm + lrow) * Kw16 + ch0;
            const int4* Bg = reinterpret_cast<const int4*>(g_wq) +
                             (size_t)(bn + lrow) * Kw16 + ch0;

            int acc[8][8];
#pragma unroll
            for (int i = 0; i < 8; i++)
#pragma unroll
                for (int jj = 0; jj < 8; jj++) acc[i][jj] = 0;

            // prologue: store stage 0 into buf0, prefetch stage 1
            int4 pa0 = Ag[0], pa1 = Ag[1];
            int4 pb0 = Bg[0], pb1 = Bg[1];
            {
                int* As = buf0;
                int* Bs = buf0 + BKW * 128;
                As[(wa + 0) * 128 + lrow] = pa0.x;
                As[(wa + 1) * 128 + lrow] = pa0.y;
                As[(wa + 2) * 128 + lrow] = pa0.z;
                As[(wa + 3) * 128 + lrow] = pa0.w;
                As[(wa + 4) * 128 + lrow] = pa1.x;
                As[(wa + 5) * 128 + lrow] = pa1.y;
                As[(wa + 6) * 128 + lrow] = pa1.z;
                As[(wa + 7) * 128 + lrow] = pa1.w;
                Bs[(wa + 0) * 128 + lrow] = pb0.x;
                Bs[(wa + 1) * 128 + lrow] = pb0.y;
                Bs[(wa + 2) * 128 + lrow] = pb0.z;
                Bs[(wa + 3) * 128 + lrow] = pb0.w;
                Bs[(wa + 4) * 128 + lrow] = pb1.x;
                Bs[(wa + 5) * 128 + lrow] = pb1.y;
                Bs[(wa + 6) * 128 + lrow] = pb1.z;
                Bs[(wa + 7) * 128 + lrow] = pb1.w;
            }
            pa0 = Ag[4]; pa1 = Ag[5];
            pb0 = Bg[4]; pb1 = Bg[5];

            for (int s = 0; s < nstage; s++) {
                BAR_SYNC(2, 256);          // stage s visible; buf of s-1 free

                if (s + 1 < nstage) {      // store prefetched stage s+1
                    int* As = ((s + 1) & 1) ? buf1 : buf0;
                    int* Bs = As + BKW * 128;
                    As[(wa + 0) * 128 + lrow] = pa0.x;
                    As[(wa + 1) * 128 + lrow] = pa0.y;
                    As[(wa + 2) * 128 + lrow] = pa0.z;
                    As[(wa + 3) * 128 + lrow] = pa0.w;
                    As[(wa + 4) * 128 + lrow] = pa1.x;
                    As[(wa + 5) * 128 + lrow] = pa1.y;
                    As[(wa + 6) * 128 + lrow] = pa1.z;
                    As[(wa + 7) * 128 + lrow] = pa1.w;
                    Bs[(wa + 0) * 128 + lrow] = pb0.x;
                    Bs[(wa + 1) * 128 + lrow] = pb0.y;
                    Bs[(wa + 2) * 128 + lrow] = pb0.z;
                    Bs[(wa + 3) * 128 + lrow] = pb0.w;
                    Bs[(wa + 4) * 128 + lrow] = pb1.x;
                    Bs[(wa + 5) * 128 + lrow] = pb1.y;
                    Bs[(wa + 6) * 128 + lrow] = pb1.z;
                    Bs[(wa + 7) * 128 + lrow] = pb1.w;
                    if (s + 2 < nstage) {  // prefetch stage s+2
                        const size_t o = (size_t)(s + 2) * 4;
                        pa0 = Ag[o]; pa1 = Ag[o + 1];
                        pb0 = Bg[o]; pb1 = Bg[o + 1];
                    }
                }

                // compute stage s
                int* As = (s & 1) ? buf1 : buf0;
                int* Bs = As + BKW * 128;
#pragma unroll
                for (int kk = 0; kk < BKW; kk++) {
                    int4 af0 = *reinterpret_cast<const int4*>(&As[kk * 128 + (ty << 3)]);
                    int4 af1 = *reinterpret_cast<const int4*>(&As[kk * 128 + (ty << 3) + 4]);
                    int4 bf0 = *reinterpret_cast<const int4*>(&Bs[kk * 128 + (tx << 3)]);
                    int4 bf1 = *reinterpret_cast<const int4*>(&Bs[kk * 128 + (tx << 3) + 4]);
                    int af[8] = {af0.x, af0.y, af0.z, af0.w, af1.x, af1.y, af1.z, af1.w};
                    int bf[8] = {bf0.x, bf0.y, bf0.z, bf0.w, bf1.x, bf1.y, bf1.z, bf1.w};
#pragma unroll
                    for (int i = 0; i < 8; i++)
#pragma unroll
                        for (int jj = 0; jj < 8; jj++)
                            acc[i][jj] = __dp4a(af[i], bf[jj], acc[i][jj]);
                }
            }

            const int cn = bn + (tx << 3);
            float4 ws0 = *reinterpret_cast<const float4*>(wscale + cn);
            float4 ws1 = *reinterpret_cast<const float4*>(wscale + cn + 4);
            float4 bb0 = *reinterpret_cast<const float4*>(bias + cn);
            float4 bb1 = *reinterpret_cast<const float4*>(bias + cn + 4);
            float wsc[8] = {ws0.x, ws0.y, ws0.z, ws0.w, ws1.x, ws1.y, ws1.z, ws1.w};
            float bb[8]  = {bb0.x, bb0.y, bb0.z, bb0.w, bb1.x, bb1.y, bb1.z, bb1.w};

#pragma unroll
            for (int i = 0; i < 8; i++) {
                const int m = bm + (ty << 3) + i;
                const float xs = g_xscale[m];
                float* orow = out + (size_t)m * N + cn;
                float4 o0, o1;
                o0.x = (float)acc[i][0] * xs * wsc[0] + bb[0];
                o0.y = (float)acc[i][1] * xs * wsc[1] + bb[1];
                o0.z = (float)acc[i][2] * xs * wsc[2] + bb[2];
                o0.w = (float)acc[i][3] * xs * wsc[3] + bb[3];
                o1.x = (float)acc[i][4] * xs * wsc[4] + bb[4];
                o1.y = (float)acc[i][5] * xs * wsc[5] + bb[5];
                o1.z = (float)acc[i][6] * xs * wsc[6] + bb[6];
                o1.w = (float)acc[i][7] * xs * wsc[7] + bb[7];
                *reinterpret_cast<float4*>(orow)     = o0;
                *reinterpret_cast<float4*>(orow + 4) = o1;
            }
        }
    }
}

// ---------------------------------------------------------------------------
// Launch
// ---------------------------------------------------------------------------
extern "C" void kernel_launch(void* const* d_in, const int* in_sizes, int n_in,
                              void* d_out, int out_size) {
    const float* x      = (const float*)d_in[0];
    const int*   weight = (const int*)d_in[1];
    const float* wscale = (const float*)d_in[2];
    const float* bias   = (const float*)d_in[3];
    float*       out    = (float*)d_out;

    const int N = in_sizes[2];           // 11008
    const int K = in_sizes[1] / N;       // 4096
    const int M = in_sizes[0] / K;       // 4096

    detect_w_dtype<<<1, 32>>>(weight);   // also resets g_job

    const size_t n_out16 = ((size_t)N * K) / 16;
    pack_w<<<(unsigned)((n_out16 + 255) / 256), 256>>>(weight, n_out16);

    quant_rows<<<M, 256>>>(x, K);

    static int nsm = 0;
    if (!nsm) {
        cudaDeviceGetAttribute(&nsm, cudaDevAttrMultiProcessorCount, 0);
        if (nsm <= 0) nsm = 148;
        cudaFuncSetAttribute(gemm_hybrid,
                             cudaFuncAttributeMaxDynamicSharedMemorySize,
                             SM_TOTAL);
    }
    gemm_hybrid<<<nsm, 512, SM_TOTAL>>>(wscale, bias, out, M, N, K);
}

// round 17
// speedup vs baseline: 1.7961x; 1.0258x over previous
#include <cuda_runtime.h>
#include <cstdint>
#include <cstddef>

// ---------------------------------------------------------------------------
// W8A8 dynamic linear — persistent hybrid IMMA + dp4a, dynamic shared queue.
//   IMMA half: 3-stage cp.async ring, 256B K-stages (16 stages), 1 bar/stage.
//   dp4a half: BKW=16 double-buffered, 1 bar/stage, conflict-free B padding.
//   x [M,K] fp32 -> per-row dynamic int8 quant (scale = maxabs/127, >=1e-8)
//   weight [N,K] int8 (harness widens to int32; detected + packed)
//   out [M,N] fp32 = (xq @ wq^T) * x_scale[m] * w_scale[n] + bias[n]
// Static shapes: M=4096, K=4096, N=11008.
// ---------------------------------------------------------------------------

#define MAXM 4096
#define MAXK 4096
#define MAXN 11008

#define M_TILES 32                     // M/128
#define N_TILES 86                     // N/128
#define NJOBS (M_TILES * N_TILES)      // 2752

__device__ int8_t g_xq[(size_t)MAXM * MAXK];          // 16 MB
__device__ float  g_xscale[MAXM];
__device__ int8_t g_wq[(size_t)MAXN * MAXK];          // 43 MB
__device__ int    g_w_widened;
__device__ unsigned int g_job;                        // dynamic tile queue

// ------------------------------ helpers ------------------------------------
__device__ __forceinline__ uint32_t smem_u32(const void* p) {
    uint32_t a;
    asm("{ .reg .u64 t; cvta.to.shared.u64 t, %1; cvt.u32.u64 %0, t; }"
        : "=r"(a) : "l"(p));
    return a;
}

__device__ __forceinline__ uint32_t swz(uint32_t o) {   // SW128 swizzle
    return o ^ ((o >> 3) & 0x70);
}

__device__ __forceinline__ void cp_async16(uint32_t dst, const void* src) {
    asm volatile("cp.async.cg.shared.global [%0], [%1], 16;"
                 :: "r"(dst), "l"(src) : "memory");
}
#define CP_ASYNC_COMMIT() asm volatile("cp.async.commit_group;" ::: "memory")
#define CP_ASYNC_WAIT(n)  asm volatile("cp.async.wait_group %0;" :: "n"(n) : "memory")

#define BAR_SYNC(id, cnt) \
    asm volatile("bar.sync %0, %1;" :: "r"(id), "r"(cnt) : "memory")

__device__ __forceinline__ void ldsm_x4(uint32_t& r0, uint32_t& r1,
                                        uint32_t& r2, uint32_t& r3,
                                        uint32_t addr) {
    asm volatile("ldmatrix.sync.aligned.m8n8.x4.shared.b16 {%0,%1,%2,%3}, [%4];"
                 : "=r"(r0), "=r"(r1), "=r"(r2), "=r"(r3) : "r"(addr));
}

__device__ __forceinline__ void imma16832(int* d, const uint32_t* a,
                                          const uint32_t* b) {
    asm volatile(
        "mma.sync.aligned.m16n8k32.row.col.s32.s8.s8.s32 "
        "{%0,%1,%2,%3}, {%4,%5,%6,%7}, {%8,%9}, {%0,%1,%2,%3};"
        : "+r"(d[0]), "+r"(d[1]), "+r"(d[2]), "+r"(d[3])
        : "r"(a[0]), "r"(a[1]), "r"(a[2]), "r"(a[3]), "r"(b[0]), "r"(b[1]));
}

// ---------------------------------------------------------------------------
// Kernel 0a: detect weight dtype + reset job counter.
// ---------------------------------------------------------------------------
__global__ void detect_w_dtype(const int* __restrict__ w) {
    if (threadIdx.x == 0) g_job = 0;
    int bad = 0;
    for (int i = threadIdx.x; i < 8192; i += 32) {
        int v = w[i];
        bad |= (v < -128 || v > 127) ? 1 : 0;
    }
#pragma unroll
    for (int o = 16; o > 0; o >>= 1)
        bad |= __shfl_xor_sync(0xffffffffu, bad, o);
    if (threadIdx.x == 0) g_w_widened = bad ? 0 : 1;
}

// ---------------------------------------------------------------------------
// Kernel 0b: pack weights int32 -> int8 (or copy if already packed).
// ---------------------------------------------------------------------------
__device__ __forceinline__ int pack4(int4 v) {
    return (v.x & 0xff) | ((v.y & 0xff) << 8) | ((v.z & 0xff) << 16) | (v.w << 24);
}

__global__ __launch_bounds__(256) void pack_w(const int* __restrict__ w,
                                              size_t n_out16) {
    const size_t i = (size_t)blockIdx.x * 256 + threadIdx.x;
    if (i >= n_out16) return;
    int4 outv;
    if (g_w_widened) {
        const int4* src = reinterpret_cast<const int4*>(w) + i * 4;
        outv.x = pack4(src[0]);
        outv.y = pack4(src[1]);
        outv.z = pack4(src[2]);
        outv.w = pack4(src[3]);
    } else {
        outv = reinterpret_cast<const int4*>(w)[i];
    }
    reinterpret_cast<int4*>(g_wq)[i] = outv;
}

// ---------------------------------------------------------------------------
// Kernel 1: per-row maxabs -> scale -> RNE quantize -> pack.
// ---------------------------------------------------------------------------
__global__ __launch_bounds__(256) void quant_rows(const float* __restrict__ x,
                                                  int K) {
    const int m = blockIdx.x;
    const int t = threadIdx.x;
    const int K4 = K >> 2;
    const float4* __restrict__ xrow =
        reinterpret_cast<const float4*>(x + (size_t)m * K);

    float amax = 0.0f;
    for (int i = t; i < K4; i += 256) {
        float4 v = xrow[i];
        amax = fmaxf(amax, fmaxf(fmaxf(fabsf(v.x), fabsf(v.y)),
                                 fmaxf(fabsf(v.z), fabsf(v.w))));
    }

    __shared__ float red[8];
#pragma unroll
    for (int o = 16; o > 0; o >>= 1)
        amax = fmaxf(amax, __shfl_xor_sync(0xffffffffu, amax, o));
    if ((t & 31) == 0) red[t >> 5] = amax;
    __syncthreads();
    if (t < 32) {
        float a = (t < 8) ? red[t] : 0.0f;
#pragma unroll
        for (int o = 4; o > 0; o >>= 1)
            a = fmaxf(a, __shfl_xor_sync(0xffffffffu, a, o));
        if (t == 0) red[0] = a;
    }
    __syncthreads();

    const float scale = fmaxf(red[0] / 127.0f, 1e-8f);
    if (t == 0) g_xscale[m] = scale;

    int* __restrict__ outw = reinterpret_cast<int*>(g_xq + (size_t)m * K);
    for (int i = t; i < K4; i += 256) {
        float4 v = xrow[i];
        int q0 = min(127, max(-128, __float2int_rn(v.x / scale)));
        int q1 = min(127, max(-128, __float2int_rn(v.y / scale)));
        int q2 = min(127, max(-128, __float2int_rn(v.z / scale)));
        int q3 = min(127, max(-128, __float2int_rn(v.w / scale)));
        outw[i] = (q0 & 0xff) | ((q1 & 0xff) << 8) | ((q2 & 0xff) << 16)
                | (q3 << 24);
    }
}

// ---------------------------------------------------------------------------
// Kernel 2: persistent hybrid GEMM, dynamic queue.
// SMEM: IMMA ring 3 x (A 32K | B 32K) = 192K; dp4a 2 x 17K; job slots.
// ---------------------------------------------------------------------------
#define RING_STRIDE 65536              // A(32K) + B(32K) per ring slot
#define SUB 16384                      // 128B-K subtile size
#define SM_RING 0                      // slots at 0, 64K, 128K
#define SM_D    196608                 // dp4a: 2 x (As 8192 + Bs 9216)
#define DBUF_STRIDE 17408
#define BS_ROW 144                     // padded Bs row stride (words)
#define SM_JOB  231424
#define SM_TOTAL (SM_JOB + 32)

#define BKW 16   // dp4a: int32 words of K per stage (= 64 int8)

__global__ __launch_bounds__(512, 1)
void gemm_hybrid(const float* __restrict__ wscale,
                 const float* __restrict__ bias,
                 float* __restrict__ out,
                 int M, int N, int K) {
    extern __shared__ __align__(1024) char smem[];
    const uint32_t sbase = smem_u32(smem);
    volatile unsigned* jslot = reinterpret_cast<volatile unsigned*>(smem + SM_JOB);

    const int tid = threadIdx.x;
    const int Kw16 = K >> 4;

    if (tid < 256) {
        // ===== IMMA half (warps 0-7), 3-stage ring of 256B-K, 1 bar/stage ==
        const int t   = tid;
        const int wid = t >> 5;
        const int lid = t & 31;
        const int wm  = wid >> 2;             // 0..1
        const int wn  = wid & 3;              // 0..3

        const int cg = t & 7;
        const int r0 = t >> 3;

        const int4* Abase = reinterpret_cast<const int4*>(g_xq) + cg;
        const int4* Bbase = reinterpret_cast<const int4*>(g_wq) + cg;

        uint32_t swo[4];
#pragma unroll
        for (int i = 0; i < 4; i++)
            swo[i] = swz((uint32_t)(r0 + 32 * i) * 128u + (uint32_t)cg * 16u);

        const uint32_t ring0 = sbase + SM_RING;
        const uint32_t ring1 = ring0 + RING_STRIDE;
        const uint32_t ring2 = ring1 + RING_STRIDE;

        const int nstage = K / 256;           // 16
        const int lrow_off = (lid & 7) + ((lid >> 3) & 1) * 8;
        const int lchunk   = lid >> 4;
        const int g   = lid >> 2;
        const int q   = lid & 3;

        int bm = 0, bn = 0;
        auto issue = [&](int kc, uint32_t slotbase) {
#pragma unroll
            for (int h = 0; h < 2; h++) {
                const int4* Ag = Abase + (size_t)(kc * 16 + h * 8);
                const int4* Bg = Bbase + (size_t)(kc * 16 + h * 8);
                const uint32_t ab = slotbase + (uint32_t)h * SUB;
                const uint32_t bb = slotbase + 32768u + (uint32_t)h * SUB;
#pragma unroll
                for (int i = 0; i < 4; i++) {
                    cp_async16(ab + swo[i],
                               Ag + (size_t)(bm + r0 + 32 * i) * Kw16);
                    cp_async16(bb + swo[i],
                               Bg + (size_t)(bn + r0 + 32 * i) * Kw16);
                }
            }
            CP_ASYNC_COMMIT();
        };

        for (;;) {
            if (t == 0) jslot[0] = atomicAdd(&g_job, 1u);
            BAR_SYNC(1, 256);                 // also separates jobs (ring reuse)
            const unsigned j = jslot[0];
            if (j >= NJOBS) break;
            bm = (int)(j & (M_TILES - 1)) * 128;
            bn = (int)(j >> 5) * 128;

            int acc[4][4][4];
#pragma unroll
            for (int i = 0; i < 4; i++)
#pragma unroll
                for (int jj = 0; jj < 4; jj++)
#pragma unroll
                    for (int qq = 0; qq < 4; qq++) acc[i][jj][qq] = 0;

            issue(0, ring0);
            issue(1, ring1);

            int ci = 0;                       // kc % 3
            for (int kc = 0; kc < nstage; kc++) {
                if (kc < nstage - 1) { CP_ASYNC_WAIT(1); }
                else                { CP_ASYNC_WAIT(0); }
                BAR_SYNC(1, 256);             // stage kc visible to all warps

                const uint32_t slot =
                    (ci == 0) ? ring0 : ((ci == 1) ? ring1 : ring2);

#pragma unroll
                for (int h = 0; h < 2; h++) {
                    const uint32_t sA = slot + (uint32_t)h * SUB;
                    const uint32_t sB = slot + 32768u + (uint32_t)h * SUB;
#pragma unroll
                    for (int s = 0; s < 4; s++) {
                        const int c = s * 2 + lchunk;
                        uint32_t a[4][4];
#pragma unroll
                        for (int ma = 0; ma < 4; ma++) {
                            const uint32_t row =
                                (uint32_t)(wm * 64 + ma * 16 + lrow_off);
                            ldsm_x4(a[ma][0], a[ma][1], a[ma][2], a[ma][3],
                                    sA + swz(row * 128u + (uint32_t)c * 16u));
                        }
                        uint32_t b[4][2];
#pragma unroll
                        for (int nb = 0; nb < 2; nb++) {
                            const uint32_t row =
                                (uint32_t)(wn * 32 + nb * 16 + lrow_off);
                            uint32_t q0, q1, q2, q3;
                            ldsm_x4(q0, q1, q2, q3,
                                    sB + swz(row * 128u + (uint32_t)c * 16u));
                            b[2 * nb][0] = q0; b[2 * nb][1] = q2;
                            b[2 * nb + 1][0] = q1; b[2 * nb + 1][1] = q3;
                        }
#pragma unroll
                        for (int ma = 0; ma < 4; ma++)
#pragma unroll
                            for (int na = 0; na < 4; na++)
                                imma16832(acc[ma][na], a[ma], b[na]);
                    }
                }

                // issue kc+2 into slot (kc+2)%3 == (kc-1)%3 — safe: the BAR
                // above proved all warps finished computing kc-1.
                if (kc + 2 < nstage) {
                    const int ii = (ci + 2 >= 3) ? ci - 1 : ci + 2;
                    const uint32_t islot =
                        (ii == 0) ? ring0 : ((ii == 1) ? ring1 : ring2);
                    issue(kc + 2, islot);
                }
                ci = (ci + 1 >= 3) ? 0 : ci + 1;
            }

            // epilogue
#pragma unroll
            for (int ma = 0; ma < 4; ma++) {
                const int m0 = bm + wm * 64 + ma * 16 + g;
                const int m1 = m0 + 8;
                const float xs0 = g_xscale[m0];
                const float xs1 = g_xscale[m1];
                float* row0 = out + (size_t)m0 * N;
                float* row1 = out + (size_t)m1 * N;
#pragma unroll
                for (int na = 0; na < 4; na++) {
                    const int n = bn + wn * 32 + na * 8 + q * 2;
                    const float ws0 = __ldg(wscale + n);
                    const float ws1 = __ldg(wscale + n + 1);
                    const float bb0 = __ldg(bias + n);
                    const float bb1 = __ldg(bias + n + 1);
                    float2 o0, o1;
                    o0.x = (float)acc[ma][na][0] * xs0 * ws0 + bb0;
                    o0.y = (float)acc[ma][na][1] * xs0 * ws1 + bb1;
                    o1.x = (float)acc[ma][na][2] * xs1 * ws0 + bb0;
                    o1.y = (float)acc[ma][na][3] * xs1 * ws1 + bb1;
                    *reinterpret_cast<float2*>(row0 + n) = o0;
                    *reinterpret_cast<float2*>(row1 + n) = o1;
                }
            }
        }
    } else {
        // ===== dp4a half (warps 8-15), BKW=16, 2 bufs, padded Bs ===========
        const int t = tid - 256;

        const int tx = t & 15;
        const int ty = t >> 4;
        const int lrow = t >> 1;           // 0..127: row this thread fills
        const int ch0  = (t & 1) * 2;      // int4 cols {0,1} or {2,3} of stage
        const int wa   = ch0 * 4;          // first word column
        // padded B row index: insert 4 pad words after every 32 rows
        const int plrow = lrow + ((lrow >> 5) << 2);
        // reader: conflict-free B offset for tx
        const int bro = tx * 8 + ((tx >> 2) << 2);

        const int nstage = (K >> 2) / BKW; // 64 stages of 64B

        int* buf0 = reinterpret_cast<int*>(smem + SM_D);
        int* buf1 = reinterpret_cast<int*>(smem + SM_D + DBUF_STRIDE);

        for (;;) {
            if (t == 0) jslot[1] = atomicAdd(&g_job, 1u);
            BAR_SYNC(2, 256);
            const unsigned j = jslot[1];
            if (j >= NJOBS) break;
            const int bm = (int)(j & (M_TILES - 1)) * 128;
            const int bn = (int)(j >> 5) * 128;

            const int4* Ag = reinterpret_cast<const int4*>(g_xq) +
                             (size_t)(bm + lrow) * Kw16 + ch0;
            const int4* Bg = reinterpret_cast<const int4*>(g_wq) +
                             (size_t)(bn + lrow) * Kw16 + ch0;

            int acc[8][8];
#pragma unroll
            for (int i = 0; i < 8; i++)
#pragma unroll
                for (int jj = 0; jj < 8; jj++) acc[i][jj] = 0;

            // prologue: store stage 0 into buf0, prefetch stage 1
            int4 pa0 = Ag[0], pa1 = Ag[1];
            int4 pb0 = Bg[0], pb1 = Bg[1];
            {
                int* As = buf0;
                int* Bs = buf0 + BKW * 128;
                As[(wa + 0) * 128 + lrow] = pa0.x;
                As[(wa + 1) * 128 + lrow] = pa0.y;
                As[(wa + 2) * 128 + lrow] = pa0.z;
                As[(wa + 3) * 128 + lrow] = pa0.w;
                As[(wa + 4) * 128 + lrow] = pa1.x;
                As[(wa + 5) * 128 + lrow] = pa1.y;
                As[(wa + 6) * 128 + lrow] = pa1.z;
                As[(wa + 7) * 128 + lrow] = pa1.w;
                Bs[(wa + 0) * BS_ROW + plrow] = pb0.x;
                Bs[(wa + 1) * BS_ROW + plrow] = pb0.y;
                Bs[(wa + 2) * BS_ROW + plrow] = pb0.z;
                Bs[(wa + 3) * BS_ROW + plrow] = pb0.w;
                Bs[(wa + 4) * BS_ROW + plrow] = pb1.x;
                Bs[(wa + 5) * BS_ROW + plrow] = pb1.y;
                Bs[(wa + 6) * BS_ROW + plrow] = pb1.z;
                Bs[(wa + 7) * BS_ROW + plrow] = pb1.w;
            }
            pa0 = Ag[4]; pa1 = Ag[5];
            pb0 = Bg[4]; pb1 = Bg[5];

            for (int s = 0; s < nstage; s++) {
                BAR_SYNC(2, 256);          // stage s visible; buf of s-1 free

                if (s + 1 < nstage) {      // store prefetched stage s+1
                    int* As = ((s + 1) & 1) ? buf1 : buf0;
                    int* Bs = As + BKW * 128;
                    As[(wa + 0) * 128 + lrow] = pa0.x;
                    As[(wa + 1) * 128 + lrow] = pa0.y;
                    As[(wa + 2) * 128 + lrow] = pa0.z;
                    As[(wa + 3) * 128 + lrow] = pa0.w;
                    As[(wa + 4) * 128 + lrow] = pa1.x;
                    As[(wa + 5) * 128 + lrow] = pa1.y;
                    As[(wa + 6) * 128 + lrow] = pa1.z;
                    As[(wa + 7) * 128 + lrow] = pa1.w;
                    Bs[(wa + 0) * BS_ROW + plrow] = pb0.x;
                    Bs[(wa + 1) * BS_ROW + plrow] = pb0.y;
                    Bs[(wa + 2) * BS_ROW + plrow] = pb0.z;
                    Bs[(wa + 3) * BS_ROW + plrow] = pb0.w;
                    Bs[(wa + 4) * BS_ROW + plrow] = pb1.x;
                    Bs[(wa + 5) * BS_ROW + plrow] = pb1.y;
                    Bs[(wa + 6) * BS_ROW + plrow] = pb1.z;
                    Bs[(wa + 7) * BS_ROW + plrow] = pb1.w;
                    if (s + 2 < nstage) {  // prefetch stage s+2
                        const size_t o = (size_t)(s + 2) * 4;
                        pa0 = Ag[o]; pa1 = Ag[o + 1];
                        pb0 = Bg[o]; pb1 = Bg[o + 1];
                    }
                }

                // compute stage s
                int* As = (s & 1) ? buf1 : buf0;
                int* Bs = As + BKW * 128;
#pragma unroll
                for (int kk = 0; kk < BKW; kk++) {
                    int4 af0 = *reinterpret_cast<const int4*>(&As[kk * 128 + (ty << 3)]);
                    int4 af1 = *reinterpret_cast<const int4*>(&As[kk * 128 + (ty << 3) + 4]);
                    int4 bf0 = *reinterpret_cast<const int4*>(&Bs[kk * BS_ROW + bro]);
                    int4 bf1 = *reinterpret_cast<const int4*>(&Bs[kk * BS_ROW + bro + 4]);
                    int af[8] = {af0.x, af0.y, af0.z, af0.w, af1.x, af1.y, af1.z, af1.w};
                    int bf[8] = {bf0.x, bf0.y, bf0.z, bf0.w, bf1.x, bf1.y, bf1.z, bf1.w};
#pragma unroll
                    for (int i = 0; i < 8; i++)
#pragma unroll
                        for (int jj = 0; jj < 8; jj++)
                            acc[i][jj] = __dp4a(af[i], bf[jj], acc[i][jj]);
                }
            }

            const int cn = bn + (tx << 3);
            float4 ws0 = *reinterpret_cast<const float4*>(wscale + cn);
            float4 ws1 = *reinterpret_cast<const float4*>(wscale + cn + 4);
            float4 bb0 = *reinterpret_cast<const float4*>(bias + cn);
            float4 bb1 = *reinterpret_cast<const float4*>(bias + cn + 4);
            float wsc[8] = {ws0.x, ws0.y, ws0.z, ws0.w, ws1.x, ws1.y, ws1.z, ws1.w};
            float bb[8]  = {bb0.x, bb0.y, bb0.z, bb0.w, bb1.x, bb1.y, bb1.z, bb1.w};

#pragma unroll
            for (int i = 0; i < 8; i++) {
                const int m = bm + (ty << 3) + i;
                const float xs = g_xscale[m];
                float* orow = out + (size_t)m * N + cn;
                float4 o0, o1;
                o0.x = (float)acc[i][0] * xs * wsc[0] + bb[0];
                o0.y = (float)acc[i][1] * xs * wsc[1] + bb[1];
                o0.z = (float)acc[i][2] * xs * wsc[2] + bb[2];
                o0.w = (float)acc[i][3] * xs * wsc[3] + bb[3];
                o1.x = (float)acc[i][4] * xs * wsc[4] + bb[4];
                o1.y = (float)acc[i][5] * xs * wsc[5] + bb[5];
                o1.z = (float)acc[i][6] * xs * wsc[6] + bb[6];
                o1.w = (float)acc[i][7] * xs * wsc[7] + bb[7];
                *reinterpret_cast<float4*>(orow)     = o0;
                *reinterpret_cast<float4*>(orow + 4) = o1;
            }
        }
    }
}

// ---------------------------------------------------------------------------
// Launch
// ---------------------------------------------------------------------------
extern "C" void kernel_launch(void* const* d_in, const int* in_sizes, int n_in,
                              void* d_out, int out_size) {
    const float* x      = (const float*)d_in[0];
    const int*   weight = (const int*)d_in[1];
    const float* wscale = (const float*)d_in[2];
    const float* bias   = (const float*)d_in[3];
    float*       out    = (float*)d_out;

    const int N = in_sizes[2];           // 11008
    const int K = in_sizes[1] / N;       // 4096
    const int M = in_sizes[0] / K;       // 4096

    detect_w_dtype<<<1, 32>>>(weight);   // also resets g_job

    const size_t n_out16 = ((size_t)N * K) / 16;
    pack_w<<<(unsigned)((n_out16 + 255) / 256), 256>>>(weight, n_out16);

    quant_rows<<<M, 256>>>(x, K);

    static int nsm = 0;
    if (!nsm) {
        cudaDeviceGetAttribute(&nsm, cudaDevAttrMultiProcessorCount, 0);
        if (nsm <= 0) nsm = 148;
        cudaFuncSetAttribute(gemm_hybrid,
                             cudaFuncAttributeMaxDynamicSharedMemorySize,
                             SM_TOTAL);
    }
    gemm_hybrid<<<nsm, 512, SM_TOTAL>>>(wscale, bias, out, M, N, K);
}